// round 4
// baseline (speedup 1.0000x reference)
#include <cuda_runtime.h>
#include <math.h>

// Problem constants
#define BB 256
#define TT 512
#define II 64
#define HH 256
#define G4 1024            // 4*H

// Scan decomposition
#define NGROUPS 16         // batch groups
#define CPG 8              // CTAs per group (hidden split)
#define MB 16              // batches per group
#define HSL 32             // hidden units per CTA
#define NROWS 128          // 4*HSL gate rows per CTA

// Scratch (static device arrays; no allocation allowed)
__device__ float g_xp[134217728];   // [B*T, 1024] = 536 MB, reused for both layers
__device__ float g_h1[33554432];    // [B, T, 256] = 134 MB, layer0 out, then layer1 out
__device__ float g_hbuf[2 * BB * HH];
__device__ int   g_bar[NGROUPS];

// ---------------------------------------------------------------------------
// Reset: zero h double-buffer + group barrier counters (fresh per launch)
// ---------------------------------------------------------------------------
__global__ void reset_kernel() {
    int i = blockIdx.x * blockDim.x + threadIdx.x;
    if (i < 2 * BB * HH) g_hbuf[i] = 0.0f;
    if (i < NGROUPS) g_bar[i] = 0;
}

// ---------------------------------------------------------------------------
// GEMM with bias: C[M,1024] = A[M,K] @ W[1024,K]^T + b1 + b2
// 128x128 tile, BK=8, 256 threads, 8x8 microtile
// ---------------------------------------------------------------------------
template <int K>
__global__ void __launch_bounds__(256) gemm_bias_kernel(
    const float* __restrict__ A, const float* __restrict__ W,
    const float* __restrict__ b1, const float* __restrict__ b2,
    float* __restrict__ C)
{
    __shared__ float As[8][128];
    __shared__ float Bs[8][132];

    int tid = threadIdx.x;
    int bm = blockIdx.y * 128;
    int bn = blockIdx.x * 128;
    int lr = tid >> 1;            // 0..127
    int lk = (tid & 1) * 4;       // 0 or 4
    int ty = tid >> 4;            // 0..15 (row tile)
    int tx = tid & 15;            // 0..15 (col tile)

    float acc[8][8];
#pragma unroll
    for (int i = 0; i < 8; i++)
#pragma unroll
        for (int j = 0; j < 8; j++) acc[i][j] = 0.0f;

    for (int kt = 0; kt < K; kt += 8) {
        float4 av = *(const float4*)&A[(size_t)(bm + lr) * K + kt + lk];
        float4 wv = *(const float4*)&W[(size_t)(bn + lr) * K + kt + lk];
        __syncthreads();
        As[lk + 0][lr] = av.x; As[lk + 1][lr] = av.y;
        As[lk + 2][lr] = av.z; As[lk + 3][lr] = av.w;
        Bs[lk + 0][lr] = wv.x; Bs[lk + 1][lr] = wv.y;
        Bs[lk + 2][lr] = wv.z; Bs[lk + 3][lr] = wv.w;
        __syncthreads();
#pragma unroll
        for (int k = 0; k < 8; k++) {
            float ar[8], br[8];
            *(float4*)&ar[0] = *(const float4*)&As[k][ty * 8];
            *(float4*)&ar[4] = *(const float4*)&As[k][ty * 8 + 4];
            *(float4*)&br[0] = *(const float4*)&Bs[k][tx * 8];
            *(float4*)&br[4] = *(const float4*)&Bs[k][tx * 8 + 4];
#pragma unroll
            for (int i = 0; i < 8; i++)
#pragma unroll
                for (int j = 0; j < 8; j++) acc[i][j] += ar[i] * br[j];
        }
    }

    float bias[8];
#pragma unroll
    for (int j = 0; j < 8; j++) {
        int n = bn + tx * 8 + j;
        bias[j] = b1[n] + b2[n];
    }
#pragma unroll
    for (int i = 0; i < 8; i++) {
        size_t row = (size_t)(bm + ty * 8 + i) * 1024 + bn + tx * 8;
        float4 v0 = make_float4(acc[i][0] + bias[0], acc[i][1] + bias[1],
                                acc[i][2] + bias[2], acc[i][3] + bias[3]);
        float4 v1 = make_float4(acc[i][4] + bias[4], acc[i][5] + bias[5],
                                acc[i][6] + bias[6], acc[i][7] + bias[7]);
        *(float4*)&C[row] = v0;
        *(float4*)&C[row + 4] = v1;
    }
}

// ---------------------------------------------------------------------------
// Persistent LSTM scan (one layer). Grid = 128 CTAs (16 groups x 8), 256 thr.
// Each CTA: hidden slice of 32 (128 gate rows of Whh cached in smem),
// 16 batches per group; c state in registers; spin barrier per group per step.
// ---------------------------------------------------------------------------
// smem: Whh tile 128x64 f4 + h tile 16x65 f4 (pad) + gates 16x132 f
#define SCAN_SMEM ((128 * 64 + 16 * 65) * 16 + 16 * 132 * 4)

__device__ __forceinline__ float sigf(float x) {
    return 1.0f / (1.0f + __expf(-x));
}

__global__ void __launch_bounds__(256, 1) scan_kernel(
    const float* __restrict__ xp,    // [B*T, 1024] precomputed input proj + biases
    const float* __restrict__ whh,   // [1024, 256]
    float* __restrict__ out_seq)     // [B, T, 256]
{
    extern __shared__ float4 smem[];
    float4* w_s4 = smem;                              // 128 rows x 64 f4 (swizzled)
    float4* h_s4 = smem + 128 * 64;                   // 16 batches x 65 f4 (stride pad)
    float*  gates = (float*)(smem + 128 * 64 + 16 * 65); // [16][132]

    int tid = threadIdx.x;
    int grp = blockIdx.x >> 3;
    int cta = blockIdx.x & 7;

    // Fill Whh slice into shared (once). Local row lr = q*32 + hloc,
    // global row = q*256 + cta*32 + hloc. k-swizzle by bit3 of lr to break
    // the r/r+8 bank collision in the compute loop.
    const float4* whh4 = (const float4*)whh;
    for (int idx = tid; idx < NROWS * 64; idx += 256) {
        int lr = idx >> 6, k4 = idx & 63;
        int q = lr >> 5, hl = lr & 31;
        int gr = q * HH + cta * HSL + hl;
        int swz = ((lr >> 3) & 1) << 2;
        w_s4[lr * 64 + (k4 ^ swz)] = whh4[(size_t)gr * 64 + k4];
    }

    // GEMM-phase thread roles: k-split 2, 8-row x 2-batch tile
    int ks = tid & 1;
    int t2 = tid >> 1;
    int b2 = t2 & 7;                 // batches b2 and b2+8
    int rb = (t2 >> 3) << 3;         // row base (8 rows)
    const int k4base = ks << 5;

    // Activation-phase roles: pairs (pb0, ph0) and (pb0+8, ph0)
    int pb0 = tid >> 5;
    int ph0 = tid & 31;
    float creg[2] = {0.0f, 0.0f};

    const float4* hb4 = (const float4*)g_hbuf;
    float* hbw = g_hbuf;

    __syncthreads();

    for (int t = 0; t < TT; ++t) {
        int cur = t & 1, nxt = cur ^ 1;

        // Load h_prev tile (bypass L1: cross-CTA data)
        for (int i = tid; i < MB * 64; i += 256) {
            int b = i >> 6, k4 = i & 63;
            h_s4[b * 65 + k4] =
                __ldcg(&hb4[(size_t)cur * BB * 64 + (grp * MB + b) * 64 + k4]);
        }
        __syncthreads();

        // gates_partial[16 rows-of-tile, 2 batches] = Whh_slice @ h
        float acc[16];
#pragma unroll
        for (int i = 0; i < 16; i++) acc[i] = 0.0f;

#pragma unroll 4
        for (int kk = 0; kk < 32; ++kk) {
            int k4 = k4base + kk;
            float4 h0 = h_s4[b2 * 65 + k4];
            float4 h1 = h_s4[(b2 + 8) * 65 + k4];
#pragma unroll
            for (int j = 0; j < 8; ++j) {
                int lr = rb + j;
                int swz = ((lr >> 3) & 1) << 2;
                float4 w = w_s4[lr * 64 + (k4 ^ swz)];
                acc[j * 2]     += w.x * h0.x + w.y * h0.y + w.z * h0.z + w.w * h0.w;
                acc[j * 2 + 1] += w.x * h1.x + w.y * h1.y + w.z * h1.z + w.w * h1.w;
            }
        }

        // k-split reduce (partner = lane^1) and write gates to smem
#pragma unroll
        for (int j = 0; j < 8; ++j) {
            float s0 = acc[j * 2]     + __shfl_xor_sync(0xffffffffu, acc[j * 2], 1);
            float s1 = acc[j * 2 + 1] + __shfl_xor_sync(0xffffffffu, acc[j * 2 + 1], 1);
            if (ks == 0) {
                gates[b2 * 132 + rb + j] = s0;
                gates[(b2 + 8) * 132 + rb + j] = s1;
            }
        }
        __syncthreads();

        // Elementwise LSTM cell for pairs (pb0, ph0) and (pb0+8, ph0)
#pragma unroll
        for (int pp = 0; pp < 2; ++pp) {
            int b = pb0 + pp * 8;
            int bg = grp * MB + b;
            size_t xoff = ((size_t)bg * TT + t) * G4 + cta * HSL + ph0;
            float iv = gates[b * 132 +       ph0] + xp[xoff];
            float fv = gates[b * 132 + 32 +  ph0] + xp[xoff + 256];
            float gv = gates[b * 132 + 64 +  ph0] + xp[xoff + 512];
            float ov = gates[b * 132 + 96 +  ph0] + xp[xoff + 768];
            float cn = sigf(fv) * creg[pp] + sigf(iv) * tanhf(gv);
            float hn = sigf(ov) * tanhf(cn);
            creg[pp] = cn;
            int hg = cta * HSL + ph0;
            hbw[(size_t)nxt * BB * HH + (size_t)bg * HH + hg] = hn;
            out_seq[((size_t)bg * TT + t) * HH + hg] = hn;
        }

        // Group barrier (monotonic counter, reset by reset_kernel per launch)
        __threadfence();
        __syncthreads();
        if (tid == 0) {
            atomicAdd(&g_bar[grp], 1);
            int tgt = CPG * (t + 1);
            while (atomicAdd(&g_bar[grp], 0) < tgt) __nanosleep(40);
            __threadfence();
        }
        __syncthreads();
    }
}

// ---------------------------------------------------------------------------
// Final FC: out[b] = dot(h2[b, T-1, :], Wfc) + bfc
// ---------------------------------------------------------------------------
__global__ void fc_kernel(const float* __restrict__ hseq,
                          const float* __restrict__ wfc,
                          const float* __restrict__ bfc,
                          float* __restrict__ out)
{
    int w = (blockIdx.x * blockDim.x + threadIdx.x) >> 5;
    int lane = threadIdx.x & 31;
    if (w >= BB) return;
    const float* hp = hseq + ((size_t)w * TT + (TT - 1)) * HH;
    float s = 0.0f;
#pragma unroll
    for (int h = lane; h < HH; h += 32) s += hp[h] * wfc[h];
#pragma unroll
    for (int o = 16; o; o >>= 1) s += __shfl_xor_sync(0xffffffffu, s, o);
    if (lane == 0) out[w] = s + bfc[0];
}

// ---------------------------------------------------------------------------
extern "C" void kernel_launch(void* const* d_in, const int* in_sizes, int n_in,
                              void* d_out, int out_size)
{
    const float* x    = (const float*)d_in[0];
    const float* Wih0 = (const float*)d_in[1];
    const float* Whh0 = (const float*)d_in[2];
    const float* bih0 = (const float*)d_in[3];
    const float* bhh0 = (const float*)d_in[4];
    const float* Wih1 = (const float*)d_in[5];
    const float* Whh1 = (const float*)d_in[6];
    const float* bih1 = (const float*)d_in[7];
    const float* bhh1 = (const float*)d_in[8];
    const float* Wfc  = (const float*)d_in[9];
    const float* bfc  = (const float*)d_in[10];
    float* out = (float*)d_out;

    float *xp, *h1;
    cudaGetSymbolAddress((void**)&xp, g_xp);
    cudaGetSymbolAddress((void**)&h1, g_h1);

    cudaFuncSetAttribute(scan_kernel,
                         cudaFuncAttributeMaxDynamicSharedMemorySize, SCAN_SMEM);

    dim3 gg(8, (BB * TT) / 128);  // N/128 x M/128

    // Layer 0
    reset_kernel<<<512, 256>>>();
    gemm_bias_kernel<II><<<gg, 256>>>(x, Wih0, bih0, bhh0, xp);
    scan_kernel<<<NGROUPS * CPG, 256, SCAN_SMEM>>>(xp, Whh0, h1);

    // Layer 1 (xp buffer reused; h1 overwritten in place by scan — safe,
    // since xp1 is fully materialized before the scan reads/writes h1)
    gemm_bias_kernel<HH><<<gg, 256>>>(h1, Wih1, bih1, bhh1, xp);
    reset_kernel<<<512, 256>>>();
    scan_kernel<<<NGROUPS * CPG, 256, SCAN_SMEM>>>(xp, Whh1, h1);

    // FC head
    fc_kernel<<<32, 256>>>(h1, Wfc, bfc, out);
}